// round 15
// baseline (speedup 1.0000x reference)
#include <cuda_runtime.h>
#include <cuda_bf16.h>
#include <cstdint>

// ---------------- problem constants ----------------
#define SEQ   8192
#define EMB   768
#define HD    512          // per-direction hidden
#define G4    2048         // 4*HD
#define NTAG  14
#define START_IDX 12
#define STOP_IDX  13
#define NEGBIG (-1e30f)

#define REC_BLOCKS_PER_DIR 64   // 64+64 = 128 CTAs of 256 thr, all co-resident
#define CHUNK  64               // CRF chunk length
#define NCHUNK (SEQ / CHUNK)    // 128

// ---------------- device scratch (static; no allocations) ----------------
__device__ float    g_xg[2][SEQ * G4];          // gate-interleaved [t][dim][gate]
__device__ float    g_hs[2][SEQ * HD];          // hidden states (for feats)
__device__ float    g_feats[SEQ * NTAG];
__device__ float    g_hbuf[2][2][HD];           // [dir][buf][dim]
__device__ __align__(256) unsigned g_flag[2][64]; // per-CTA step flags (2 lines/dir)
__device__ float    g_chunkM[NCHUNK][NTAG][NTAG];

// ---------------- helpers ----------------
__device__ __forceinline__ float sigf(float x) {
    return __fdividef(1.0f, 1.0f + __expf(-x));
}
__device__ __forceinline__ float tanh_fast(float x) {
    float a = fabsf(x);
    float e = __expf(-2.0f * a);                 // in (0,1], never overflows
    float t = __fdividef(1.0f - e, 1.0f + e);
    return copysignf(t, x);
}

// =====================================================================
// 1) GEMM: xg[dir] = embeds @ w_ih^T (+ b_ih + b_hh), gate-interleaved
//    (R2 simple single-buffer version — measured fastest, FROZEN)
// =====================================================================
#define BM 128
#define BN 128
#define BK 16
__global__ void __launch_bounds__(256, 2) gemm_xg(
    const float* __restrict__ emb,
    const float* __restrict__ wih_f, const float* __restrict__ bih_f, const float* __restrict__ bhh_f,
    const float* __restrict__ wih_b, const float* __restrict__ bih_b, const float* __restrict__ bhh_b)
{
    const int dir = blockIdx.z;
    const float* __restrict__ W  = dir ? wih_b : wih_f;
    const float* __restrict__ b1 = dir ? bih_b : bih_f;
    const float* __restrict__ b2 = dir ? bhh_b : bhh_f;
    float* __restrict__ out = g_xg[dir];

    __shared__ float As[BK][BM + 4];
    __shared__ float Bs[BK][BN + 4];

    const int tx = threadIdx.x;                  // 0..255
    const int m0 = blockIdx.y * BM;
    const int n0 = blockIdx.x * BN;
    const int tm = (tx >> 4) * 8;
    const int tn = (tx & 15) * 8;

    float acc[8][8] = {};

    for (int k0 = 0; k0 < EMB; k0 += BK) {
        #pragma unroll
        for (int i = 0; i < 2; i++) {
            int idx = tx + i * 256;
            int r   = idx >> 2;
            int c4  = (idx & 3) * 4;
            float4 v = *(const float4*)&emb[(m0 + r) * EMB + k0 + c4];
            As[c4 + 0][r] = v.x; As[c4 + 1][r] = v.y;
            As[c4 + 2][r] = v.z; As[c4 + 3][r] = v.w;
        }
        #pragma unroll
        for (int i = 0; i < 2; i++) {
            int idx = tx + i * 256;
            int r   = idx >> 2;
            int c4  = (idx & 3) * 4;
            float4 v = *(const float4*)&W[(n0 + r) * EMB + k0 + c4];
            Bs[c4 + 0][r] = v.x; Bs[c4 + 1][r] = v.y;
            Bs[c4 + 2][r] = v.z; Bs[c4 + 3][r] = v.w;
        }
        __syncthreads();
        #pragma unroll
        for (int kk = 0; kk < BK; kk++) {
            float a[8], b[8];
            #pragma unroll
            for (int i = 0; i < 8; i++) a[i] = As[kk][tm + i];
            #pragma unroll
            for (int j = 0; j < 8; j++) b[j] = Bs[kk][tn + j];
            #pragma unroll
            for (int i = 0; i < 8; i++)
                #pragma unroll
                for (int j = 0; j < 8; j++)
                    acc[i][j] = fmaf(a[i], b[j], acc[i][j]);
        }
        __syncthreads();
    }

    #pragma unroll
    for (int i = 0; i < 8; i++) {
        int t = m0 + tm + i;
        #pragma unroll
        for (int j = 0; j < 8; j++) {
            int r = n0 + tn + j;
            out[t * G4 + ((r & (HD - 1)) << 2) + (r >> 9)] = acc[i][j] + b1[r] + b2[r];
        }
    }
}

// =====================================================================
// 2) init: h0 into buffers, reset flags (runs every launch/replay)
// =====================================================================
__global__ void init_state(const float* __restrict__ h0)
{
    int i = threadIdx.x;                         // 512 threads
    g_hbuf[0][0][i] = h0[i];
    g_hbuf[1][0][i] = h0[HD + i];
    if (i < 128) g_flag[i >> 6][i & 63] = 0u;
}

// =====================================================================
// 3) BiLSTM recurrence: R2 structure; barrier = per-CTA FLAG STORES
//    (no atomics -> no L2 atomic-ALU serialization of 64 arrivals)
// =====================================================================
__global__ void __launch_bounds__(256, 1) lstm_rec(
    const float* __restrict__ whh_f,
    const float* __restrict__ whh_b,
    const float* __restrict__ c0)
{
    const int dir = blockIdx.x >> 6;             // 64 blocks per direction
    const int blk = blockIdx.x & 63;
    const int w   = threadIdx.x >> 5;            // warp 0..7
    const int l   = threadIdx.x & 31;
    const int j   = blk * 8 + w;                 // owned h-dim

    const float* __restrict__ W  = dir ? whh_b : whh_f;
    const float* __restrict__ xg = g_xg[dir];
    float* __restrict__ hs = g_hs[dir];
    float* hb0 = g_hbuf[dir][0];
    float* hb1 = g_hbuf[dir][1];
    unsigned* flg = &g_flag[dir][0];

    // weights register-resident; lane l covers k = l, l+32, ..., l+480
    float wr[4][16];
    #pragma unroll
    for (int g = 0; g < 4; g++) {
        const float* wrow = &W[(g * HD + j) * HD];
        #pragma unroll
        for (int kk = 0; kk < 16; kk++) wr[g][kk] = wrow[kk * 32 + l];
    }
    float c = c0[dir * HD + j];

    __shared__ float hsh[HD];

    // stage initial h (2 floats / thread)
    {
        float2 v = __ldcg((const float2*)&hb0[threadIdx.x * 2]);
        hsh[threadIdx.x * 2 + 0] = v.x;
        hsh[threadIdx.x * 2 + 1] = v.y;
    }
    __syncthreads();

    // prefetch xg for step 0 (broadcast load, warp-uniform address)
    int s0 = dir ? (SEQ - 1) : 0;
    float4 xv = *(const float4*)&xg[s0 * G4 + j * 4];

    for (int t = 0; t < SEQ; t++) {
        const int s = dir ? (SEQ - 1 - t) : t;

        // prefetch next step's xg early (hides DRAM latency by a full step)
        float4 xv_next;
        if (t + 1 < SEQ) {
            int sn = dir ? (SEQ - 2 - t) : (t + 1);
            xv_next = *(const float4*)&xg[sn * G4 + j * 4];
        } else {
            xv_next = make_float4(0.f, 0.f, 0.f, 0.f);
        }

        // h chunk from smem
        float h[16];
        #pragma unroll
        for (int kk = 0; kk < 16; kk++) h[kk] = hsh[kk * 32 + l];

        float d0 = 0.f, d1 = 0.f, d2 = 0.f, d3 = 0.f;
        #pragma unroll
        for (int kk = 0; kk < 16; kk++) {
            d0 = fmaf(wr[0][kk], h[kk], d0);
            d1 = fmaf(wr[1][kk], h[kk], d1);
            d2 = fmaf(wr[2][kk], h[kk], d2);
            d3 = fmaf(wr[3][kk], h[kk], d3);
        }
        #pragma unroll
        for (int off = 16; off > 0; off >>= 1) {
            d0 += __shfl_down_sync(0xffffffffu, d0, off);
            d1 += __shfl_down_sync(0xffffffffu, d1, off);
            d2 += __shfl_down_sync(0xffffffffu, d2, off);
            d3 += __shfl_down_sync(0xffffffffu, d3, off);
        }

        float* hdst = (t & 1) ? hb0 : hb1;
        if (l == 0) {
            float gi = xv.x + d0;
            float gf = xv.y + d1;
            float gg = xv.z + d2;
            float go = xv.w + d3;
            c = sigf(gf) * c + sigf(gi) * tanh_fast(gg);
            float hn = sigf(go) * tanh_fast(c);
            __stcg(&hdst[j], hn);                // L2-visible for other SMs
            hs[s * HD + j] = hn;
        }
        xv = xv_next;

        __syncthreads();                          // block's h stores done
        if (w == 0) {
            if (l == 0) {
                __threadfence();                  // order h stores before flag
                __stcg(&flg[blk], (unsigned)(t + 1));   // own word: plain store
            }
            // 32 lanes poll all 64 flags via 2 coalesced loads (2 lines)
            const unsigned want = (unsigned)(t + 1);
            const volatile unsigned* vf = flg;
            bool ok;
            do {
                unsigned a = vf[l];
                unsigned b = vf[l + 32];
                ok = (a >= want) && (b >= want);  // >= : producers may run ahead
            } while (!__all_sync(0xffffffffu, ok));
        }
        __syncthreads();

        // stage the just-produced h for the next step
        if (t + 1 < SEQ) {
            const float* hsrc = (t & 1) ? hb0 : hb1;
            float2 v = __ldcg((const float2*)&hsrc[threadIdx.x * 2]);
            hsh[threadIdx.x * 2 + 0] = v.x;
            hsh[threadIdx.x * 2 + 1] = v.y;
            __syncthreads();
        }
    }
}

// =====================================================================
// 4) feats[t, j] = [hs_f | hs_b] . w_tag[j] + b_tag[j]
// =====================================================================
__global__ void feats_kernel(const float* __restrict__ w_tag,
                             const float* __restrict__ b_tag)
{
    const int t = blockIdx.x;
    const int w = threadIdx.x >> 5;              // 0..13 (tag)
    const int l = threadIdx.x & 31;
    const float* __restrict__ hf = &g_hs[0][t * HD];
    const float* __restrict__ hb = &g_hs[1][t * HD];
    const float* __restrict__ wt = &w_tag[w * 1024];

    float acc = 0.f;
    #pragma unroll
    for (int k = l; k < HD; k += 32)
        acc = fmaf(hf[k], wt[k], fmaf(hb[k], wt[HD + k], acc));
    #pragma unroll
    for (int off = 16; off > 0; off >>= 1)
        acc += __shfl_down_sync(0xffffffffu, acc, off);
    if (l == 0) g_feats[t * NTAG + w] = acc + b_tag[w];
}

// =====================================================================
// 5) CRF chunk matrices (log-semiring): Ms <- M_t (o) Ms, 64 steps/chunk
// =====================================================================
__global__ void crf_chunk(const float* __restrict__ trans)
{
    __shared__ float Ms[NTAG][NTAG + 2];
    const int tid = threadIdx.x;                 // 0..195
    const int j = tid / NTAG;
    const int i = tid % NTAG;

    float trow[NTAG];
    #pragma unroll
    for (int k = 0; k < NTAG; k++) trow[k] = trans[j * NTAG + k];

    Ms[j][i] = (i == j) ? 0.f : NEGBIG;          // semiring identity
    __syncthreads();

    const int base = blockIdx.x * CHUNK;
    for (int t = base; t < base + CHUNK; t++) {
        float fj = g_feats[t * NTAG + j];
        float vals[NTAG];
        float m = NEGBIG;
        #pragma unroll
        for (int k = 0; k < NTAG; k++) {
            vals[k] = trow[k] + Ms[k][i];
            m = fmaxf(m, vals[k]);
        }
        float s = 0.f;
        #pragma unroll
        for (int k = 0; k < NTAG; k++) s += __expf(vals[k] - m);
        float nv = m + __logf(s) + fj;
        __syncthreads();
        Ms[j][i] = nv;
        __syncthreads();
    }
    g_chunkM[blockIdx.x][j][i] = Ms[j][i];
}

// =====================================================================
// 6) gold score (parallel reduce) + chunk composition + final output
// =====================================================================
__global__ void crf_final(const float* __restrict__ trans,
                          const int* __restrict__ tags,
                          float* __restrict__ out)
{
    __shared__ float red[256];
    const int tid = threadIdx.x;

    float part = 0.f;
    for (int t = tid; t < SEQ; t += 256) {
        int tag  = tags[t];
        int prev = (t == 0) ? START_IDX : tags[t - 1];
        part += g_feats[t * NTAG + tag] + trans[tag * NTAG + prev];
    }
    red[tid] = part;
    __syncthreads();
    #pragma unroll
    for (int s = 128; s > 0; s >>= 1) {
        if (tid < s) red[tid] += red[tid + s];
        __syncthreads();
    }
    const float gold = red[0] + trans[STOP_IDX * NTAG + tags[SEQ - 1]];

    if (tid < 32) {
        const int l = tid;
        float fv = (l < NTAG) ? ((l == START_IDX) ? 0.f : NEGBIG) : NEGBIG;
        for (int cix = 0; cix < NCHUNK; cix++) {
            float vals[NTAG];
            float m = NEGBIG;
            #pragma unroll
            for (int i = 0; i < NTAG; i++) {
                float fvi = __shfl_sync(0xffffffffu, fv, i);
                float v = (l < NTAG) ? (g_chunkM[cix][l][i] + fvi) : NEGBIG;
                vals[i] = v;
                m = fmaxf(m, v);
            }
            float s = 0.f;
            #pragma unroll
            for (int i = 0; i < NTAG; i++) s += __expf(vals[i] - m);
            float nv = m + __logf(s);
            fv = (l < NTAG) ? nv : NEGBIG;
        }
        float v = (l < NTAG) ? (fv + trans[STOP_IDX * NTAG + l]) : NEGBIG;
        float m = v;
        #pragma unroll
        for (int off = 16; off > 0; off >>= 1)
            m = fmaxf(m, __shfl_xor_sync(0xffffffffu, m, off));
        float e = __expf(v - m);
        #pragma unroll
        for (int off = 16; off > 0; off >>= 1)
            e += __shfl_xor_sync(0xffffffffu, e, off);
        float fwd = m + __logf(e);
        if (l == 0) out[0] = fwd - gold;
    }
}

// =====================================================================
// launch
// =====================================================================
extern "C" void kernel_launch(void* const* d_in, const int* in_sizes, int n_in,
                              void* d_out, int out_size)
{
    const float* embeds = (const float*)d_in[0];
    const int*   tags   = (const int*)  d_in[1];
    const float* w_ih_f = (const float*)d_in[2];
    const float* w_hh_f = (const float*)d_in[3];
    const float* b_ih_f = (const float*)d_in[4];
    const float* b_hh_f = (const float*)d_in[5];
    const float* w_ih_b = (const float*)d_in[6];
    const float* w_hh_b = (const float*)d_in[7];
    const float* b_ih_b = (const float*)d_in[8];
    const float* b_hh_b = (const float*)d_in[9];
    const float* w_tag  = (const float*)d_in[10];
    const float* b_tag  = (const float*)d_in[11];
    const float* trans  = (const float*)d_in[12];
    const float* h0     = (const float*)d_in[13];
    const float* c0     = (const float*)d_in[14];
    float* out = (float*)d_out;

    dim3 gemm_grid(G4 / BN, SEQ / BM, 2);        // (16, 64, 2)
    gemm_xg<<<gemm_grid, 256>>>(embeds,
                                w_ih_f, b_ih_f, b_hh_f,
                                w_ih_b, b_ih_b, b_hh_b);

    init_state<<<1, 512>>>(h0);

    lstm_rec<<<2 * REC_BLOCKS_PER_DIR, 256>>>(w_hh_f, w_hh_b, c0);

    feats_kernel<<<SEQ, NTAG * 32>>>(w_tag, b_tag);

    crf_chunk<<<NCHUNK, NTAG * NTAG>>>(trans);

    crf_final<<<1, 256>>>(trans, tags, out);
}

// round 16
// speedup vs baseline: 2.5292x; 2.5292x over previous
#include <cuda_runtime.h>
#include <cuda_bf16.h>
#include <cstdint>

// ---------------- problem constants ----------------
#define SEQ   8192
#define EMB   768
#define HD    512          // per-direction hidden
#define G4    2048         // 4*HD
#define NTAG  14
#define START_IDX 12
#define STOP_IDX  13
#define NEGBIG (-1e30f)

#define REC_BLOCKS_PER_DIR 64   // 64+64 = 128 CTAs of 256 thr, all co-resident
#define CHUNK  64               // CRF chunk length
#define NCHUNK (SEQ / CHUNK)    // 128

// ---------------- device scratch (static; no allocations) ----------------
__device__ float    g_xg[2][SEQ * G4];          // gate-interleaved [t][dim][gate]
__device__ float    g_hs[2][SEQ * HD];          // hidden states (for feats)
__device__ float    g_feats[SEQ * NTAG];
__device__ float    g_hbuf[2][2][HD];           // [dir][buf][dim]
__device__ unsigned g_bar[2][32];               // per-direction counter (128B apart)
__device__ float    g_chunkM[NCHUNK][NTAG][NTAG];

// ---------------- helpers ----------------
__device__ __forceinline__ float sigf(float x) {
    return __fdividef(1.0f, 1.0f + __expf(-x));
}
__device__ __forceinline__ float tanh_fast(float x) {
    float a = fabsf(x);
    float e = __expf(-2.0f * a);                 // in (0,1], never overflows
    float t = __fdividef(1.0f - e, 1.0f + e);
    return copysignf(t, x);
}
__device__ __forceinline__ uint32_t f2tf32(float x) {
    uint32_t r;
    asm("cvt.rna.tf32.f32 %0, %1;" : "=r"(r) : "f"(x));
    return r;
}

// =====================================================================
// 1) GEMM via tensor cores (tf32 mma.sync m16n8k8):
//    xg[dir] = embeds @ w_ih^T (+ b_ih + b_hh), gate-interleaved.
//    Same tiling + smem staging as the frozen R2 GEMM; only the inner
//    product moved from FFMA to HMMA.
// =====================================================================
#define BM 128
#define BN 128
#define BK 16
__global__ void __launch_bounds__(256, 2) gemm_xg(
    const float* __restrict__ emb,
    const float* __restrict__ wih_f, const float* __restrict__ bih_f, const float* __restrict__ bhh_f,
    const float* __restrict__ wih_b, const float* __restrict__ bih_b, const float* __restrict__ bhh_b)
{
    const int dir = blockIdx.z;
    const float* __restrict__ W  = dir ? wih_b : wih_f;
    const float* __restrict__ b1 = dir ? bih_b : bih_f;
    const float* __restrict__ b2 = dir ? bhh_b : bhh_f;
    float* __restrict__ out = g_xg[dir];

    __shared__ float As[BK][BM + 4];             // [k][m]
    __shared__ float Bs[BK][BN + 4];             // [k][n]  (n = w_ih row r)

    const int tx = threadIdx.x;                  // 0..255
    const int m0 = blockIdx.y * BM;
    const int n0 = blockIdx.x * BN;

    const int wid  = tx >> 5;
    const int lane = tx & 31;
    const int warp_m = (wid >> 1) * 32;          // 0,32,64,96
    const int warp_n = (wid & 1) * 64;           // 0,64
    const int g  = lane >> 2;                    // groupID 0..7
    const int tg = lane & 3;                     // thread-in-group 0..3

    float acc[2][8][4];                          // [mi][ni][c0..c3]
    #pragma unroll
    for (int mi = 0; mi < 2; mi++)
        #pragma unroll
        for (int ni = 0; ni < 8; ni++)
            #pragma unroll
            for (int c = 0; c < 4; c++) acc[mi][ni][c] = 0.f;

    for (int k0 = 0; k0 < EMB; k0 += BK) {
        // stage tiles (identical addressing to the proven R2 GEMM loads)
        #pragma unroll
        for (int i = 0; i < 2; i++) {
            int idx = tx + i * 256;
            int r   = idx >> 2;
            int c4  = (idx & 3) * 4;
            float4 v = *(const float4*)&emb[(m0 + r) * EMB + k0 + c4];
            As[c4 + 0][r] = v.x; As[c4 + 1][r] = v.y;
            As[c4 + 2][r] = v.z; As[c4 + 3][r] = v.w;
        }
        #pragma unroll
        for (int i = 0; i < 2; i++) {
            int idx = tx + i * 256;
            int r   = idx >> 2;
            int c4  = (idx & 3) * 4;
            float4 v = *(const float4*)&W[(n0 + r) * EMB + k0 + c4];
            Bs[c4 + 0][r] = v.x; Bs[c4 + 1][r] = v.y;
            Bs[c4 + 2][r] = v.z; Bs[c4 + 3][r] = v.w;
        }
        __syncthreads();

        #pragma unroll
        for (int ks = 0; ks < 2; ks++) {
            const int kb = ks * 8;
            // A fragments: a0:(g,tg) a1:(g+8,tg) a2:(g,tg+4) a3:(g+8,tg+4)
            uint32_t a[2][4];
            #pragma unroll
            for (int mi = 0; mi < 2; mi++) {
                const int mr = warp_m + mi * 16;
                a[mi][0] = f2tf32(As[kb + tg    ][mr + g    ]);
                a[mi][1] = f2tf32(As[kb + tg    ][mr + g + 8]);
                a[mi][2] = f2tf32(As[kb + tg + 4][mr + g    ]);
                a[mi][3] = f2tf32(As[kb + tg + 4][mr + g + 8]);
            }
            #pragma unroll
            for (int ni = 0; ni < 8; ni++) {
                const int nc = warp_n + ni * 8;
                // B fragments: b0:(k=tg, n=g)  b1:(k=tg+4, n=g)
                uint32_t b0 = f2tf32(Bs[kb + tg    ][nc + g]);
                uint32_t b1 = f2tf32(Bs[kb + tg + 4][nc + g]);
                #pragma unroll
                for (int mi = 0; mi < 2; mi++) {
                    asm volatile(
                        "mma.sync.aligned.m16n8k8.row.col.f32.tf32.tf32.f32 "
                        "{%0,%1,%2,%3}, {%4,%5,%6,%7}, {%8,%9}, {%0,%1,%2,%3};"
                        : "+f"(acc[mi][ni][0]), "+f"(acc[mi][ni][1]),
                          "+f"(acc[mi][ni][2]), "+f"(acc[mi][ni][3])
                        : "r"(a[mi][0]), "r"(a[mi][1]), "r"(a[mi][2]), "r"(a[mi][3]),
                          "r"(b0), "r"(b1));
                }
            }
        }
        __syncthreads();
    }

    // store with gate-interleave remap: row r -> [t*2048 + (r&511)*4 + (r>>9)]
    // acc layout: c0:(g, 2tg) c1:(g, 2tg+1) c2:(g+8, 2tg) c3:(g+8, 2tg+1)
    #pragma unroll
    for (int mi = 0; mi < 2; mi++) {
        #pragma unroll
        for (int ni = 0; ni < 8; ni++) {
            const int t0 = m0 + warp_m + mi * 16 + g;
            const int t1 = t0 + 8;
            const int r0 = n0 + warp_n + ni * 8 + 2 * tg;
            const int r1 = r0 + 1;
            const int o0 = ((r0 & (HD - 1)) << 2) + (r0 >> 9);
            const int o1 = ((r1 & (HD - 1)) << 2) + (r1 >> 9);
            const float bb0 = b1[r0] + b2[r0];
            const float bb1 = b1[r1] + b2[r1];
            out[t0 * G4 + o0] = acc[mi][ni][0] + bb0;
            out[t0 * G4 + o1] = acc[mi][ni][1] + bb1;
            out[t1 * G4 + o0] = acc[mi][ni][2] + bb0;
            out[t1 * G4 + o1] = acc[mi][ni][3] + bb1;
        }
    }
}

// =====================================================================
// 2) init: h0 into buffers, reset counters (runs every launch/replay)
// =====================================================================
__global__ void init_state(const float* __restrict__ h0)
{
    int i = threadIdx.x;                         // 512 threads
    g_hbuf[0][0][i] = h0[i];
    g_hbuf[1][0][i] = h0[HD + i];
    if (i < 2) g_bar[i][0] = 0u;
}

// =====================================================================
// 3) BiLSTM recurrence: R2 byte-for-byte (FROZEN — empirically optimal)
// =====================================================================
__global__ void __launch_bounds__(256, 1) lstm_rec(
    const float* __restrict__ whh_f,
    const float* __restrict__ whh_b,
    const float* __restrict__ c0)
{
    const int dir = blockIdx.x >> 6;             // 64 blocks per direction
    const int blk = blockIdx.x & 63;
    const int w   = threadIdx.x >> 5;            // warp 0..7
    const int l   = threadIdx.x & 31;
    const int j   = blk * 8 + w;                 // owned h-dim

    const float* __restrict__ W  = dir ? whh_b : whh_f;
    const float* __restrict__ xg = g_xg[dir];
    float* __restrict__ hs = g_hs[dir];
    float* hb0 = g_hbuf[dir][0];
    float* hb1 = g_hbuf[dir][1];
    unsigned* bar = &g_bar[dir][0];

    // weights register-resident; lane l covers k = l, l+32, ..., l+480
    float wr[4][16];
    #pragma unroll
    for (int g = 0; g < 4; g++) {
        const float* wrow = &W[(g * HD + j) * HD];
        #pragma unroll
        for (int kk = 0; kk < 16; kk++) wr[g][kk] = wrow[kk * 32 + l];
    }
    float c = c0[dir * HD + j];

    __shared__ float hsh[HD];

    // stage initial h (2 floats / thread)
    {
        float2 v = __ldcg((const float2*)&hb0[threadIdx.x * 2]);
        hsh[threadIdx.x * 2 + 0] = v.x;
        hsh[threadIdx.x * 2 + 1] = v.y;
    }
    __syncthreads();

    // prefetch xg for step 0 (broadcast load, warp-uniform address)
    int s0 = dir ? (SEQ - 1) : 0;
    float4 xv = *(const float4*)&xg[s0 * G4 + j * 4];

    for (int t = 0; t < SEQ; t++) {
        const int s = dir ? (SEQ - 1 - t) : t;

        // prefetch next step's xg early (hides DRAM latency by a full step)
        float4 xv_next;
        if (t + 1 < SEQ) {
            int sn = dir ? (SEQ - 2 - t) : (t + 1);
            xv_next = *(const float4*)&xg[sn * G4 + j * 4];
        } else {
            xv_next = make_float4(0.f, 0.f, 0.f, 0.f);
        }

        // h chunk from smem
        float h[16];
        #pragma unroll
        for (int kk = 0; kk < 16; kk++) h[kk] = hsh[kk * 32 + l];

        float d0 = 0.f, d1 = 0.f, d2 = 0.f, d3 = 0.f;
        #pragma unroll
        for (int kk = 0; kk < 16; kk++) {
            d0 = fmaf(wr[0][kk], h[kk], d0);
            d1 = fmaf(wr[1][kk], h[kk], d1);
            d2 = fmaf(wr[2][kk], h[kk], d2);
            d3 = fmaf(wr[3][kk], h[kk], d3);
        }
        #pragma unroll
        for (int off = 16; off > 0; off >>= 1) {
            d0 += __shfl_down_sync(0xffffffffu, d0, off);
            d1 += __shfl_down_sync(0xffffffffu, d1, off);
            d2 += __shfl_down_sync(0xffffffffu, d2, off);
            d3 += __shfl_down_sync(0xffffffffu, d3, off);
        }

        float* hdst = (t & 1) ? hb0 : hb1;
        if (l == 0) {
            float gi = xv.x + d0;
            float gf = xv.y + d1;
            float gg = xv.z + d2;
            float go = xv.w + d3;
            c = sigf(gf) * c + sigf(gi) * tanh_fast(gg);
            float hn = sigf(go) * tanh_fast(c);
            __stcg(&hdst[j], hn);                // L2-visible for other SMs
            hs[s * HD + j] = hn;
        }
        xv = xv_next;

        __syncthreads();                          // block's h stores done
        if (threadIdx.x == 0) {
            __threadfence();                      // release stores to GPU scope
            atomicAdd(bar, 1u);
            const unsigned target = (unsigned)REC_BLOCKS_PER_DIR * (unsigned)(t + 1);
            while (*(volatile unsigned*)bar < target) { }
        }
        __syncthreads();

        // stage the just-produced h for the next step
        if (t + 1 < SEQ) {
            const float* hsrc = (t & 1) ? hb0 : hb1;
            float2 v = __ldcg((const float2*)&hsrc[threadIdx.x * 2]);
            hsh[threadIdx.x * 2 + 0] = v.x;
            hsh[threadIdx.x * 2 + 1] = v.y;
            __syncthreads();
        }
    }
}

// =====================================================================
// 4) feats[t, j] = [hs_f | hs_b] . w_tag[j] + b_tag[j]
// =====================================================================
__global__ void feats_kernel(const float* __restrict__ w_tag,
                             const float* __restrict__ b_tag)
{
    const int t = blockIdx.x;
    const int w = threadIdx.x >> 5;              // 0..13 (tag)
    const int l = threadIdx.x & 31;
    const float* __restrict__ hf = &g_hs[0][t * HD];
    const float* __restrict__ hb = &g_hs[1][t * HD];
    const float* __restrict__ wt = &w_tag[w * 1024];

    float acc = 0.f;
    #pragma unroll
    for (int k = l; k < HD; k += 32)
        acc = fmaf(hf[k], wt[k], fmaf(hb[k], wt[HD + k], acc));
    #pragma unroll
    for (int off = 16; off > 0; off >>= 1)
        acc += __shfl_down_sync(0xffffffffu, acc, off);
    if (l == 0) g_feats[t * NTAG + w] = acc + b_tag[w];
}

// =====================================================================
// 5) CRF chunk matrices (log-semiring): Ms <- M_t (o) Ms, 64 steps/chunk
// =====================================================================
__global__ void crf_chunk(const float* __restrict__ trans)
{
    __shared__ float Ms[NTAG][NTAG + 2];
    const int tid = threadIdx.x;                 // 0..195
    const int j = tid / NTAG;
    const int i = tid % NTAG;

    float trow[NTAG];
    #pragma unroll
    for (int k = 0; k < NTAG; k++) trow[k] = trans[j * NTAG + k];

    Ms[j][i] = (i == j) ? 0.f : NEGBIG;          // semiring identity
    __syncthreads();

    const int base = blockIdx.x * CHUNK;
    for (int t = base; t < base + CHUNK; t++) {
        float fj = g_feats[t * NTAG + j];
        float vals[NTAG];
        float m = NEGBIG;
        #pragma unroll
        for (int k = 0; k < NTAG; k++) {
            vals[k] = trow[k] + Ms[k][i];
            m = fmaxf(m, vals[k]);
        }
        float s = 0.f;
        #pragma unroll
        for (int k = 0; k < NTAG; k++) s += __expf(vals[k] - m);
        float nv = m + __logf(s) + fj;
        __syncthreads();
        Ms[j][i] = nv;
        __syncthreads();
    }
    g_chunkM[blockIdx.x][j][i] = Ms[j][i];
}

// =====================================================================
// 6) gold score (parallel reduce) + chunk composition + final output
// =====================================================================
__global__ void crf_final(const float* __restrict__ trans,
                          const int* __restrict__ tags,
                          float* __restrict__ out)
{
    __shared__ float red[256];
    const int tid = threadIdx.x;

    float part = 0.f;
    for (int t = tid; t < SEQ; t += 256) {
        int tag  = tags[t];
        int prev = (t == 0) ? START_IDX : tags[t - 1];
        part += g_feats[t * NTAG + tag] + trans[tag * NTAG + prev];
    }
    red[tid] = part;
    __syncthreads();
    #pragma unroll
    for (int s = 128; s > 0; s >>= 1) {
        if (tid < s) red[tid] += red[tid + s];
        __syncthreads();
    }
    const float gold = red[0] + trans[STOP_IDX * NTAG + tags[SEQ - 1]];

    if (tid < 32) {
        const int l = tid;
        float fv = (l < NTAG) ? ((l == START_IDX) ? 0.f : NEGBIG) : NEGBIG;
        for (int cix = 0; cix < NCHUNK; cix++) {
            float vals[NTAG];
            float m = NEGBIG;
            #pragma unroll
            for (int i = 0; i < NTAG; i++) {
                float fvi = __shfl_sync(0xffffffffu, fv, i);
                float v = (l < NTAG) ? (g_chunkM[cix][l][i] + fvi) : NEGBIG;
                vals[i] = v;
                m = fmaxf(m, v);
            }
            float s = 0.f;
            #pragma unroll
            for (int i = 0; i < NTAG; i++) s += __expf(vals[i] - m);
            float nv = m + __logf(s);
            fv = (l < NTAG) ? nv : NEGBIG;
        }
        float v = (l < NTAG) ? (fv + trans[STOP_IDX * NTAG + l]) : NEGBIG;
        float m = v;
        #pragma unroll
        for (int off = 16; off > 0; off >>= 1)
            m = fmaxf(m, __shfl_xor_sync(0xffffffffu, m, off));
        float e = __expf(v - m);
        #pragma unroll
        for (int off = 16; off > 0; off >>= 1)
            e += __shfl_xor_sync(0xffffffffu, e, off);
        float fwd = m + __logf(e);
        if (l == 0) out[0] = fwd - gold;
    }
}

// =====================================================================
// launch
// =====================================================================
extern "C" void kernel_launch(void* const* d_in, const int* in_sizes, int n_in,
                              void* d_out, int out_size)
{
    const float* embeds = (const float*)d_in[0];
    const int*   tags   = (const int*)  d_in[1];
    const float* w_ih_f = (const float*)d_in[2];
    const float* w_hh_f = (const float*)d_in[3];
    const float* b_ih_f = (const float*)d_in[4];
    const float* b_hh_f = (const float*)d_in[5];
    const float* w_ih_b = (const float*)d_in[6];
    const float* w_hh_b = (const float*)d_in[7];
    const float* b_ih_b = (const float*)d_in[8];
    const float* b_hh_b = (const float*)d_in[9];
    const float* w_tag  = (const float*)d_in[10];
    const float* b_tag  = (const float*)d_in[11];
    const float* trans  = (const float*)d_in[12];
    const float* h0     = (const float*)d_in[13];
    const float* c0     = (const float*)d_in[14];
    float* out = (float*)d_out;

    dim3 gemm_grid(G4 / BN, SEQ / BM, 2);        // (16, 64, 2)
    gemm_xg<<<gemm_grid, 256>>>(embeds,
                                w_ih_f, b_ih_f, b_hh_f,
                                w_ih_b, b_ih_b, b_hh_b);

    init_state<<<1, 512>>>(h0);

    lstm_rec<<<2 * REC_BLOCKS_PER_DIR, 256>>>(w_hh_f, w_hh_b, c0);

    feats_kernel<<<SEQ, NTAG * 32>>>(w_tag, b_tag);

    crf_chunk<<<NCHUNK, NTAG * NTAG>>>(trans);

    crf_final<<<1, 256>>>(trans, tags, out);
}

// round 17
// speedup vs baseline: 2.6166x; 1.0345x over previous
#include <cuda_runtime.h>
#include <cuda_bf16.h>
#include <cstdint>

// ---------------- problem constants ----------------
#define SEQ   8192
#define EMB   768
#define HD    512          // per-direction hidden
#define G4    2048         // 4*HD
#define NTAG  14
#define START_IDX 12
#define STOP_IDX  13
#define NEGBIG (-1e30f)

#define REC_BLOCKS_PER_DIR 64   // 64+64 = 128 CTAs of 256 thr, all co-resident
#define CHUNK  64               // CRF chunk length
#define NCHUNK (SEQ / CHUNK)    // 128

// ---------------- device scratch (static; no allocations) ----------------
__device__ float    g_xg[2][SEQ * G4];          // NATURAL layout [t][r], r in [0,4*HD)
__device__ float    g_hs[2][SEQ * HD];          // hidden states (for feats)
__device__ float    g_feats[SEQ * NTAG];
__device__ float    g_hbuf[2][2][HD];           // [dir][buf][dim]
__device__ unsigned g_bar[2][32];               // per-direction counter (128B apart)
__device__ float    g_chunkM[NCHUNK][NTAG][NTAG];

// ---------------- helpers ----------------
__device__ __forceinline__ float sigf(float x) {
    return __fdividef(1.0f, 1.0f + __expf(-x));
}
__device__ __forceinline__ float tanh_fast(float x) {
    float a = fabsf(x);
    float e = __expf(-2.0f * a);                 // in (0,1], never overflows
    float t = __fdividef(1.0f - e, 1.0f + e);
    return copysignf(t, x);
}
__device__ __forceinline__ uint32_t f2tf32(float x) {
    uint32_t r;
    asm("cvt.rna.tf32.f32 %0, %1;" : "=r"(r) : "f"(x));
    return r;
}

// =====================================================================
// 1) GEMM via tensor cores (tf32 mma.sync m16n8k8), NATURAL output
//    layout with fully-coalesced float2 stores (no gate interleave).
// =====================================================================
#define BM 128
#define BN 128
#define BK 16
__global__ void __launch_bounds__(256, 2) gemm_xg(
    const float* __restrict__ emb,
    const float* __restrict__ wih_f, const float* __restrict__ bih_f, const float* __restrict__ bhh_f,
    const float* __restrict__ wih_b, const float* __restrict__ bih_b, const float* __restrict__ bhh_b)
{
    const int dir = blockIdx.z;
    const float* __restrict__ W  = dir ? wih_b : wih_f;
    const float* __restrict__ b1 = dir ? bih_b : bih_f;
    const float* __restrict__ b2 = dir ? bhh_b : bhh_f;
    float* __restrict__ out = g_xg[dir];

    __shared__ float As[BK][BM + 4];             // [k][m]
    __shared__ float Bs[BK][BN + 4];             // [k][n]  (n = w_ih row r)

    const int tx = threadIdx.x;                  // 0..255
    const int m0 = blockIdx.y * BM;
    const int n0 = blockIdx.x * BN;

    const int wid  = tx >> 5;
    const int lane = tx & 31;
    const int warp_m = (wid >> 1) * 32;          // 0,32,64,96
    const int warp_n = (wid & 1) * 64;           // 0,64
    const int g  = lane >> 2;                    // groupID 0..7
    const int tg = lane & 3;                     // thread-in-group 0..3

    float acc[2][8][4];                          // [mi][ni][c0..c3]
    #pragma unroll
    for (int mi = 0; mi < 2; mi++)
        #pragma unroll
        for (int ni = 0; ni < 8; ni++)
            #pragma unroll
            for (int c = 0; c < 4; c++) acc[mi][ni][c] = 0.f;

    for (int k0 = 0; k0 < EMB; k0 += BK) {
        // stage tiles (identical addressing to the proven R2 GEMM loads)
        #pragma unroll
        for (int i = 0; i < 2; i++) {
            int idx = tx + i * 256;
            int r   = idx >> 2;
            int c4  = (idx & 3) * 4;
            float4 v = *(const float4*)&emb[(m0 + r) * EMB + k0 + c4];
            As[c4 + 0][r] = v.x; As[c4 + 1][r] = v.y;
            As[c4 + 2][r] = v.z; As[c4 + 3][r] = v.w;
        }
        #pragma unroll
        for (int i = 0; i < 2; i++) {
            int idx = tx + i * 256;
            int r   = idx >> 2;
            int c4  = (idx & 3) * 4;
            float4 v = *(const float4*)&W[(n0 + r) * EMB + k0 + c4];
            Bs[c4 + 0][r] = v.x; Bs[c4 + 1][r] = v.y;
            Bs[c4 + 2][r] = v.z; Bs[c4 + 3][r] = v.w;
        }
        __syncthreads();

        #pragma unroll
        for (int ks = 0; ks < 2; ks++) {
            const int kb = ks * 8;
            // A fragments: a0:(g,tg) a1:(g+8,tg) a2:(g,tg+4) a3:(g+8,tg+4)
            uint32_t a[2][4];
            #pragma unroll
            for (int mi = 0; mi < 2; mi++) {
                const int mr = warp_m + mi * 16;
                a[mi][0] = f2tf32(As[kb + tg    ][mr + g    ]);
                a[mi][1] = f2tf32(As[kb + tg    ][mr + g + 8]);
                a[mi][2] = f2tf32(As[kb + tg + 4][mr + g    ]);
                a[mi][3] = f2tf32(As[kb + tg + 4][mr + g + 8]);
            }
            #pragma unroll
            for (int ni = 0; ni < 8; ni++) {
                const int nc = warp_n + ni * 8;
                uint32_t b0 = f2tf32(Bs[kb + tg    ][nc + g]);
                uint32_t b1v = f2tf32(Bs[kb + tg + 4][nc + g]);
                #pragma unroll
                for (int mi = 0; mi < 2; mi++) {
                    asm volatile(
                        "mma.sync.aligned.m16n8k8.row.col.f32.tf32.tf32.f32 "
                        "{%0,%1,%2,%3}, {%4,%5,%6,%7}, {%8,%9}, {%0,%1,%2,%3};"
                        : "+f"(acc[mi][ni][0]), "+f"(acc[mi][ni][1]),
                          "+f"(acc[mi][ni][2]), "+f"(acc[mi][ni][3])
                        : "r"(a[mi][0]), "r"(a[mi][1]), "r"(a[mi][2]), "r"(a[mi][3]),
                          "r"(b0), "r"(b1v));
                }
            }
        }
        __syncthreads();
    }

    // coalesced float2 stores, natural layout out[t*G4 + r]
    // acc layout: c0:(g, 2tg) c1:(g, 2tg+1) c2:(g+8, 2tg) c3:(g+8, 2tg+1)
    #pragma unroll
    for (int mi = 0; mi < 2; mi++) {
        #pragma unroll
        for (int ni = 0; ni < 8; ni++) {
            const int t0 = m0 + warp_m + mi * 16 + g;
            const int t1 = t0 + 8;
            const int r0 = n0 + warp_n + ni * 8 + 2 * tg;
            const float bb0 = b1[r0] + b2[r0];
            const float bb1 = b1[r0 + 1] + b2[r0 + 1];
            float2 v0 = make_float2(acc[mi][ni][0] + bb0, acc[mi][ni][1] + bb1);
            float2 v1 = make_float2(acc[mi][ni][2] + bb0, acc[mi][ni][3] + bb1);
            *(float2*)&out[t0 * G4 + r0] = v0;   // lanes tg=0..3 fill a 32B sector
            *(float2*)&out[t1 * G4 + r0] = v1;
        }
    }
}

// =====================================================================
// 2) init: h0 into buffers, reset counters (runs every launch/replay)
// =====================================================================
__global__ void init_state(const float* __restrict__ h0)
{
    int i = threadIdx.x;                         // 512 threads
    g_hbuf[0][0][i] = h0[i];
    g_hbuf[1][0][i] = h0[HD + i];
    if (i < 2) g_bar[i][0] = 0u;
}

// =====================================================================
// 3) BiLSTM recurrence: R2 byte-for-byte EXCEPT xv loads (natural xg:
//    4 warp-uniform scalar LDGs at j, HD+j, 2HD+j, 3HD+j, prefetched)
// =====================================================================
__global__ void __launch_bounds__(256, 1) lstm_rec(
    const float* __restrict__ whh_f,
    const float* __restrict__ whh_b,
    const float* __restrict__ c0)
{
    const int dir = blockIdx.x >> 6;             // 64 blocks per direction
    const int blk = blockIdx.x & 63;
    const int w   = threadIdx.x >> 5;            // warp 0..7
    const int l   = threadIdx.x & 31;
    const int j   = blk * 8 + w;                 // owned h-dim

    const float* __restrict__ W  = dir ? whh_b : whh_f;
    const float* __restrict__ xg = g_xg[dir];
    float* __restrict__ hs = g_hs[dir];
    float* hb0 = g_hbuf[dir][0];
    float* hb1 = g_hbuf[dir][1];
    unsigned* bar = &g_bar[dir][0];

    // weights register-resident; lane l covers k = l, l+32, ..., l+480
    float wr[4][16];
    #pragma unroll
    for (int g = 0; g < 4; g++) {
        const float* wrow = &W[(g * HD + j) * HD];
        #pragma unroll
        for (int kk = 0; kk < 16; kk++) wr[g][kk] = wrow[kk * 32 + l];
    }
    float c = c0[dir * HD + j];

    __shared__ float hsh[HD];

    // stage initial h (2 floats / thread)
    {
        float2 v = __ldcg((const float2*)&hb0[threadIdx.x * 2]);
        hsh[threadIdx.x * 2 + 0] = v.x;
        hsh[threadIdx.x * 2 + 1] = v.y;
    }
    __syncthreads();

    // prefetch xg for step 0 (4 warp-uniform scalar loads, natural layout)
    int s0 = dir ? (SEQ - 1) : 0;
    float4 xv;
    {
        const float* xr = &xg[s0 * G4 + j];
        xv.x = xr[0]; xv.y = xr[HD]; xv.z = xr[2 * HD]; xv.w = xr[3 * HD];
    }

    for (int t = 0; t < SEQ; t++) {
        const int s = dir ? (SEQ - 1 - t) : t;

        // prefetch next step's xg early (hides DRAM latency by a full step)
        float4 xv_next;
        if (t + 1 < SEQ) {
            int sn = dir ? (SEQ - 2 - t) : (t + 1);
            const float* xr = &xg[sn * G4 + j];
            xv_next.x = xr[0];
            xv_next.y = xr[HD];
            xv_next.z = xr[2 * HD];
            xv_next.w = xr[3 * HD];
        } else {
            xv_next = make_float4(0.f, 0.f, 0.f, 0.f);
        }

        // h chunk from smem
        float h[16];
        #pragma unroll
        for (int kk = 0; kk < 16; kk++) h[kk] = hsh[kk * 32 + l];

        float d0 = 0.f, d1 = 0.f, d2 = 0.f, d3 = 0.f;
        #pragma unroll
        for (int kk = 0; kk < 16; kk++) {
            d0 = fmaf(wr[0][kk], h[kk], d0);
            d1 = fmaf(wr[1][kk], h[kk], d1);
            d2 = fmaf(wr[2][kk], h[kk], d2);
            d3 = fmaf(wr[3][kk], h[kk], d3);
        }
        #pragma unroll
        for (int off = 16; off > 0; off >>= 1) {
            d0 += __shfl_down_sync(0xffffffffu, d0, off);
            d1 += __shfl_down_sync(0xffffffffu, d1, off);
            d2 += __shfl_down_sync(0xffffffffu, d2, off);
            d3 += __shfl_down_sync(0xffffffffu, d3, off);
        }

        float* hdst = (t & 1) ? hb0 : hb1;
        if (l == 0) {
            float gi = xv.x + d0;
            float gf = xv.y + d1;
            float gg = xv.z + d2;
            float go = xv.w + d3;
            c = sigf(gf) * c + sigf(gi) * tanh_fast(gg);
            float hn = sigf(go) * tanh_fast(c);
            __stcg(&hdst[j], hn);                // L2-visible for other SMs
            hs[s * HD + j] = hn;
        }
        xv = xv_next;

        __syncthreads();                          // block's h stores done
        if (threadIdx.x == 0) {
            __threadfence();                      // release stores to GPU scope
            atomicAdd(bar, 1u);
            const unsigned target = (unsigned)REC_BLOCKS_PER_DIR * (unsigned)(t + 1);
            while (*(volatile unsigned*)bar < target) { }
        }
        __syncthreads();

        // stage the just-produced h for the next step
        if (t + 1 < SEQ) {
            const float* hsrc = (t & 1) ? hb0 : hb1;
            float2 v = __ldcg((const float2*)&hsrc[threadIdx.x * 2]);
            hsh[threadIdx.x * 2 + 0] = v.x;
            hsh[threadIdx.x * 2 + 1] = v.y;
            __syncthreads();
        }
    }
}

// =====================================================================
// 4) feats[t, j] = [hs_f | hs_b] . w_tag[j] + b_tag[j]
// =====================================================================
__global__ void feats_kernel(const float* __restrict__ w_tag,
                             const float* __restrict__ b_tag)
{
    const int t = blockIdx.x;
    const int w = threadIdx.x >> 5;              // 0..13 (tag)
    const int l = threadIdx.x & 31;
    const float* __restrict__ hf = &g_hs[0][t * HD];
    const float* __restrict__ hb = &g_hs[1][t * HD];
    const float* __restrict__ wt = &w_tag[w * 1024];

    float acc = 0.f;
    #pragma unroll
    for (int k = l; k < HD; k += 32)
        acc = fmaf(hf[k], wt[k], fmaf(hb[k], wt[HD + k], acc));
    #pragma unroll
    for (int off = 16; off > 0; off >>= 1)
        acc += __shfl_down_sync(0xffffffffu, acc, off);
    if (l == 0) g_feats[t * NTAG + w] = acc + b_tag[w];
}

// =====================================================================
// 5) CRF chunk matrices (log-semiring): Ms <- M_t (o) Ms, 64 steps/chunk
// =====================================================================
__global__ void crf_chunk(const float* __restrict__ trans)
{
    __shared__ float Ms[NTAG][NTAG + 2];
    const int tid = threadIdx.x;                 // 0..195
    const int j = tid / NTAG;
    const int i = tid % NTAG;

    float trow[NTAG];
    #pragma unroll
    for (int k = 0; k < NTAG; k++) trow[k] = trans[j * NTAG + k];

    Ms[j][i] = (i == j) ? 0.f : NEGBIG;          // semiring identity
    __syncthreads();

    const int base = blockIdx.x * CHUNK;
    for (int t = base; t < base + CHUNK; t++) {
        float fj = g_feats[t * NTAG + j];
        float vals[NTAG];
        float m = NEGBIG;
        #pragma unroll
        for (int k = 0; k < NTAG; k++) {
            vals[k] = trow[k] + Ms[k][i];
            m = fmaxf(m, vals[k]);
        }
        float s = 0.f;
        #pragma unroll
        for (int k = 0; k < NTAG; k++) s += __expf(vals[k] - m);
        float nv = m + __logf(s) + fj;
        __syncthreads();
        Ms[j][i] = nv;
        __syncthreads();
    }
    g_chunkM[blockIdx.x][j][i] = Ms[j][i];
}

// =====================================================================
// 6) gold score (parallel reduce) + chunk composition + final output
// =====================================================================
__global__ void crf_final(const float* __restrict__ trans,
                          const int* __restrict__ tags,
                          float* __restrict__ out)
{
    __shared__ float red[256];
    const int tid = threadIdx.x;

    float part = 0.f;
    for (int t = tid; t < SEQ; t += 256) {
        int tag  = tags[t];
        int prev = (t == 0) ? START_IDX : tags[t - 1];
        part += g_feats[t * NTAG + tag] + trans[tag * NTAG + prev];
    }
    red[tid] = part;
    __syncthreads();
    #pragma unroll
    for (int s = 128; s > 0; s >>= 1) {
        if (tid < s) red[tid] += red[tid + s];
        __syncthreads();
    }
    const float gold = red[0] + trans[STOP_IDX * NTAG + tags[SEQ - 1]];

    if (tid < 32) {
        const int l = tid;
        float fv = (l < NTAG) ? ((l == START_IDX) ? 0.f : NEGBIG) : NEGBIG;
        for (int cix = 0; cix < NCHUNK; cix++) {
            float vals[NTAG];
            float m = NEGBIG;
            #pragma unroll
            for (int i = 0; i < NTAG; i++) {
                float fvi = __shfl_sync(0xffffffffu, fv, i);
                float v = (l < NTAG) ? (g_chunkM[cix][l][i] + fvi) : NEGBIG;
                vals[i] = v;
                m = fmaxf(m, v);
            }
            float s = 0.f;
            #pragma unroll
            for (int i = 0; i < NTAG; i++) s += __expf(vals[i] - m);
            float nv = m + __logf(s);
            fv = (l < NTAG) ? nv : NEGBIG;
        }
        float v = (l < NTAG) ? (fv + trans[STOP_IDX * NTAG + l]) : NEGBIG;
        float m = v;
        #pragma unroll
        for (int off = 16; off > 0; off >>= 1)
            m = fmaxf(m, __shfl_xor_sync(0xffffffffu, m, off));
        float e = __expf(v - m);
        #pragma unroll
        for (int off = 16; off > 0; off >>= 1)
            e += __shfl_xor_sync(0xffffffffu, e, off);
        float fwd = m + __logf(e);
        if (l == 0) out[0] = fwd - gold;
    }
}

// =====================================================================
// launch
// =====================================================================
extern "C" void kernel_launch(void* const* d_in, const int* in_sizes, int n_in,
                              void* d_out, int out_size)
{
    const float* embeds = (const float*)d_in[0];
    const int*   tags   = (const int*)  d_in[1];
    const float* w_ih_f = (const float*)d_in[2];
    const float* w_hh_f = (const float*)d_in[3];
    const float* b_ih_f = (const float*)d_in[4];
    const float* b_hh_f = (const float*)d_in[5];
    const float* w_ih_b = (const float*)d_in[6];
    const float* w_hh_b = (const float*)d_in[7];
    const float* b_ih_b = (const float*)d_in[8];
    const float* b_hh_b = (const float*)d_in[9];
    const float* w_tag  = (const float*)d_in[10];
    const float* b_tag  = (const float*)d_in[11];
    const float* trans  = (const float*)d_in[12];
    const float* h0     = (const float*)d_in[13];
    const float* c0     = (const float*)d_in[14];
    float* out = (float*)d_out;

    dim3 gemm_grid(G4 / BN, SEQ / BM, 2);        // (16, 64, 2)
    gemm_xg<<<gemm_grid, 256>>>(embeds,
                                w_ih_f, b_ih_f, b_hh_f,
                                w_ih_b, b_ih_b, b_hh_b);

    init_state<<<1, 512>>>(h0);

    lstm_rec<<<2 * REC_BLOCKS_PER_DIR, 256>>>(w_hh_f, w_hh_b, c0);

    feats_kernel<<<SEQ, NTAG * 32>>>(w_tag, b_tag);

    crf_chunk<<<NCHUNK, NTAG * NTAG>>>(trans);

    crf_final<<<1, 256>>>(trans, tags, out);
}